// round 12
// baseline (speedup 1.0000x reference)
#include <cuda_runtime.h>
#include <cuda_fp16.h>
#include <cstdint>

// R11: occupancy attack. regs 127 capped occ at 16 warps/SM (latency-bound,
// issue 29.5%). Now: launch_bounds(256,3) (<=84 regs), candidates -> gmem
// scratch, meta packed to 8B/k => SMEM 72KB => 3 CTAs/SM = 24 warps.
// Bounds re-derived for the half-rounded runtime scale (still rigorous).
// Exact rescore / epilogue / finalize statement-identical to validated path.

#define NT       131072
#define KC       1024
#define DIM      64
#define MT       256
#define THREADS  256
#define GRID_VQ  (NT/MT)          // 512
#define CAP      28

// g_pack: [0,16384) int8 codebook rows; [16384,18432) float2 meta per cw:
// {e_norm exact fp32, half2(sw*1024 inflated, Q1 = sum|q| inflated)}.
__device__ uint32_t g_pack[18432];
__device__ uint32_t g_cand[NT * CAP];      // per-token candidate scratch
__device__ float g_partials[GRID_VQ];
__device__ unsigned g_ctr = 0;

static __device__ __forceinline__ int q8(float v, float rs) {
    int q = __float2int_rn(v * rs);
    return max(-127, min(127, q));
}
static __device__ __forceinline__ uint32_t pack4(int a, int b, int c, int d) {
    return (uint32_t)(uint8_t)a | ((uint32_t)(uint8_t)b << 8) |
           ((uint32_t)(uint8_t)c << 16) | ((uint32_t)(uint8_t)d << 24);
}

// ---------------- prep: int8 quant + exact e_norm + packed bound meta ----------------
__global__ void prep_kernel(const float* __restrict__ w) {
    int k = blockIdx.x * 256 + threadIdx.x;
    if (k >= KC) return;
    const float4* r = (const float4*)(w + (size_t)k * DIM);
    float en = 0.f, amax = 0.f;
    #pragma unroll
    for (int i = 0; i < 16; i++) {
        float4 a = r[i];
        en += a.x * a.x + a.y * a.y + a.z * a.z + a.w * a.w;  // validated order
        amax = fmaxf(amax, fabsf(a.x)); amax = fmaxf(amax, fabsf(a.y));
        amax = fmaxf(amax, fabsf(a.z)); amax = fmaxf(amax, fabsf(a.w));
    }
    float sw = amax * (1.f / 127.f);
    float rs = (amax > 0.f) ? (127.f / amax) : 0.f;
    int q1 = 0;
    #pragma unroll
    for (int i = 0; i < 16; i++) {
        float4 a = r[i];
        int qa = q8(a.x, rs), qb = q8(a.y, rs), qc = q8(a.z, rs), qd = q8(a.w, rs);
        q1 += abs(qa) + abs(qb) + abs(qc) + abs(qd);
        g_pack[k * 16 + i] = pack4(qa, qb, qc, qd);
    }
    // half-packed, inflated UP so runtime values upper-bound the true ones.
    __half hs = __float2half_rn(sw * 1024.f * 1.001f);
    __half hq = __float2half_rn((float)q1 * 1.002f + 16.f);
    g_pack[16384 + 2 * k]     = __float_as_uint(en);
    g_pack[16384 + 2 * k + 1] = ((uint32_t)__half_as_ushort(hq) << 16) |
                                 (uint32_t)__half_as_ushort(hs);
}

// ---------------- main VQ kernel (finalize fused in last block) ----------------
__global__ __launch_bounds__(THREADS, 3) void vq_kernel(
    const float* __restrict__ x, const float* __restrict__ w, float* __restrict__ out)
{
    extern __shared__ uint8_t dyn[];
    uint32_t*     s_qw   = (uint32_t*)dyn;               // 65536 B
    const float2* s_meta = (const float2*)(dyn + 65536); //  8192 B
    __shared__ float s_warp[8];
    __shared__ unsigned s_ticket;

    const int tid  = threadIdx.x;
    const int gtok = blockIdx.x * MT + tid;
    const float4* xr = (const float4*)(x + (size_t)gtok * DIM);
    uint32_t* myc = g_cand + (size_t)gtok * CAP;

    // stage packed codebook + meta (4608 uint4)
    {
        const uint4* src = (const uint4*)g_pack;
        uint4* dst = (uint4*)dyn;
        #pragma unroll
        for (int i = 0; i < 18; i++) dst[i * 256 + tid] = src[i * 256 + tid];
    }

    // pass 1 over x row: amax + xn (validated accumulation order for xn)
    float xn = 0.f, amax = 0.f;
    #pragma unroll
    for (int i = 0; i < 16; i++) {
        float4 v = xr[i];
        xn += v.x * v.x + v.y * v.y + v.z * v.z + v.w * v.w;
        amax = fmaxf(amax, fabsf(v.x)); amax = fmaxf(amax, fabsf(v.y));
        amax = fmaxf(amax, fabsf(v.z)); amax = fmaxf(amax, fabsf(v.w));
    }
    // pass 2: quantize own token (L1 hits); sabs = sum|qx|
    uint32_t qx[16];
    int sabs = 0;
    const float sx = amax * (1.f / 127.f);
    {
        const float rs = (amax > 0.f) ? (127.f / amax) : 0.f;
        #pragma unroll
        for (int i = 0; i < 16; i++) {
            float4 v = xr[i];
            int a = q8(v.x, rs), b = q8(v.y, rs), c = q8(v.z, rs), d = q8(v.w, rs);
            sabs += abs(a) + abs(b) + abs(c) + abs(d);
            qx[i] = pack4(a, b, c, d);
        }
    }
    __syncthreads();

    // Rigorous bound with runtime (half-rounded) scale sw^:
    //   per-elt dequant err <= 0.8*sw^  (int8 round 0.5 + scale round <=2e-3*127)
    //   E_k = sx*sw^_k*(1.6*sabs + Q1_k + 51.2) + 1e-4
    const float cB = sx * (1.6f * (float)sabs + 51.2f);
    const float nC = -2.f * sx;
    float best_ub = 3.4e38f;
    int cnt = 0;
    #pragma unroll 2
    for (int k = 0; k < KC; k++) {
        const uint4* row = (const uint4*)(s_qw + k * 16);
        uint4 a = row[0], b = row[1], c = row[2], d = row[3];
        int p0 = 0, p1 = 0, p2 = 0, p3 = 0;
        p0 = __dp4a((int)a.x, (int)qx[0],  p0);
        p1 = __dp4a((int)a.y, (int)qx[1],  p1);
        p2 = __dp4a((int)a.z, (int)qx[2],  p2);
        p3 = __dp4a((int)a.w, (int)qx[3],  p3);
        p0 = __dp4a((int)b.x, (int)qx[4],  p0);
        p1 = __dp4a((int)b.y, (int)qx[5],  p1);
        p2 = __dp4a((int)b.z, (int)qx[6],  p2);
        p3 = __dp4a((int)b.w, (int)qx[7],  p3);
        p0 = __dp4a((int)c.x, (int)qx[8],  p0);
        p1 = __dp4a((int)c.y, (int)qx[9],  p1);
        p2 = __dp4a((int)c.z, (int)qx[10], p2);
        p3 = __dp4a((int)c.w, (int)qx[11], p3);
        p0 = __dp4a((int)d.x, (int)qx[12], p0);
        p1 = __dp4a((int)d.y, (int)qx[13], p1);
        p2 = __dp4a((int)d.z, (int)qx[14], p2);
        p3 = __dp4a((int)d.w, (int)qx[15], p3);
        int idot = (p0 + p1) + (p2 + p3);
        float2 m = s_meta[k];
        __half2 h2 = *(__half2*)&m.y;
        float swh = __half2float(__low2half(h2)) * (1.f / 1024.f);  // sw^ (>= sw)
        float q1f = __half2float(__high2half(h2));                   // Q1  (>= Q1)
        float s = fmaf(nC * swh, (float)idot, m.x);                  // approx score
        float E = fmaf(sx, q1f, cB) * swh + 1e-4f;                   // rigorous bound
        float lb = s - E;
        if (lb <= best_ub) {                                         // provable keep
            if (cnt < CAP) {
                uint32_t h = (uint32_t)__half_as_ushort(__float2half(lb));
                myc[cnt] = (h << 16) | (uint32_t)k;
            }
            cnt++;
        }
        best_ub = fminf(best_ub, s + E);
    }

    // ---- exact rescore (statement-identical to validated path) ----
    float bestex = 3.4e38f;
    int bi = 0;
    auto rescore = [&](int k) {
        const float4* wr = (const float4*)(w + (size_t)k * DIM);
        float a0 = 0.f, a1 = 0.f, a2 = 0.f, a3 = 0.f;
        #pragma unroll
        for (int p = 0; p < 16; p++) {
            float4 xv = xr[p];
            float4 wv = wr[p];
            a0 = fmaf(xv.x, wv.x, a0);
            a1 = fmaf(xv.y, wv.y, a1);
            a2 = fmaf(xv.z, wv.z, a2);
            a3 = fmaf(xv.w, wv.w, a3);
        }
        float dot = __fadd_rn(__fadd_rn(a0, a1), __fadd_rn(a2, a3));
        float s = __fadd_rn(__fadd_rn(xn, s_meta[k].x), -2.f * dot);
        if (s < bestex || (s == bestex && k < bi)) { bestex = s; bi = k; }
    };

    if (cnt > CAP) {
        for (int k = 0; k < KC; k++) rescore(k);       // rare overflow fallback
    } else {
        const float fth = best_ub + 1e-3f;             // fp16 round-up slack
        for (int i = 0; i < cnt; i++) {                // ascending k order
            uint32_t e = myc[i];                       // L2-hit readback
            float lb = __half2float(__ushort_as_half((unsigned short)(e >> 16)));
            if (lb <= fth) rescore((int)(e & 0xFFFFu));
        }
    }

    // ---- outputs (validated epilogue) ----
    const float4* wrow = (const float4*)(w + (size_t)bi * DIM);
    float4* xqo = (float4*)(out + (size_t)gtok * DIM);
    float err = 0.f;
    #pragma unroll
    for (int i = 0; i < 16; i++) {
        float4 xv = xr[i];
        float4 wv = wrow[i];
        float e0 = wv.x - xv.x, t1 = wv.y - xv.y;
        float t2 = wv.z - xv.z, t3 = wv.w - xv.w;
        err += e0 * e0 + t1 * t1 + t2 * t2 + t3 * t3;
        xqo[i] = wv;
    }
    out[(size_t)NT * DIM + 1 + gtok] = (float)bi;

    #pragma unroll
    for (int o = 16; o > 0; o >>= 1) err += __shfl_xor_sync(0xffffffffu, err, o);
    if ((tid & 31) == 0) s_warp[tid >> 5] = err;
    __syncthreads();
    if (tid == 0) {
        float s = 0.f;
        #pragma unroll
        for (int i = 0; i < 8; i++) s += s_warp[i];
        g_partials[blockIdx.x] = s;
    }

    // ---- fused finalize (identical double-reduction arithmetic) ----
    __threadfence();
    if (tid == 0) s_ticket = atomicAdd(&g_ctr, 1u);
    __syncthreads();
    if (s_ticket == GRID_VQ - 1) {
        double* sd = (double*)(dyn + 65536);   // reuse meta region (done)
        double v = 0.0;
        for (int i = tid; i < GRID_VQ; i += 256) v += (double)g_partials[i];
        sd[tid] = v;
        __syncthreads();
        for (int o = 128; o > 0; o >>= 1) {
            if (tid < o) sd[tid] += sd[tid + o];
            __syncthreads();
        }
        if (tid == 0) {
            double mse = sd[0] / ((double)NT * (double)DIM);
            out[(size_t)NT * DIM] = (float)(1.25 * mse);
            g_ctr = 0;                          // self-reset for graph replay
        }
    }
}

// pads keep vq_kernel at in-call launch index 3 (ncu -s 5 lands on vq)
__global__ void pad0_kernel() {}
__global__ void pad1_kernel() {}

extern "C" void kernel_launch(void* const* d_in, const int* in_sizes, int n_in,
                              void* d_out, int out_size) {
    const float* x = (const float*)d_in[0];
    const float* w = (const float*)d_in[1];
    float* out = (float*)d_out;
    cudaFuncSetAttribute((const void*)vq_kernel,
                         cudaFuncAttributeMaxDynamicSharedMemorySize, 73728);
    prep_kernel<<<4, 256>>>(w);
    pad0_kernel<<<1, 32>>>();
    pad1_kernel<<<1, 32>>>();
    vq_kernel<<<GRID_VQ, THREADS, 73728>>>(x, w, out);
}

// round 14
// speedup vs baseline: 1.7359x; 1.7359x over previous
#include <cuda_runtime.h>
#include <cuda_fp16.h>
#include <cstdint>

// R12: R10-tight rigorous bounds + CAP=64 gmem candidate scratch (fallback
// probability ~0) + 3 CTAs/SM. The R11 regression was warp-divergent full-KC
// fallback storms from a looser bound at CAP=28.
// Exact rescore / epilogue / finalize statement-identical to validated path.

#define NT       131072
#define KC       1024
#define DIM      64
#define MT       256
#define THREADS  256
#define GRID_VQ  (NT/MT)          // 512
#define CAP      64

// g_pack: [0,16384) int8 rows; [16384,18432) float2 {en exact, sw};
// [18432,18944) half L1w (inflated upper bound), 2/word.
__device__ uint32_t g_pack[18944];
__device__ uint32_t g_cand[(size_t)NT * CAP];   // 33.5MB candidate scratch
__device__ float g_partials[GRID_VQ];
__device__ unsigned g_ctr = 0;

static __device__ __forceinline__ int q8(float v, float rs) {
    int q = __float2int_rn(v * rs);
    return max(-127, min(127, q));
}
static __device__ __forceinline__ uint32_t pack4(int a, int b, int c, int d) {
    return (uint32_t)(uint8_t)a | ((uint32_t)(uint8_t)b << 8) |
           ((uint32_t)(uint8_t)c << 16) | ((uint32_t)(uint8_t)d << 24);
}

// ---------------- prep: int8 quant + exact e_norm + L1 upper bound ----------------
__global__ void prep_kernel(const float* __restrict__ w) {
    int k = blockIdx.x * 256 + threadIdx.x;
    if (k >= KC) return;
    const float4* r = (const float4*)(w + (size_t)k * DIM);
    float en = 0.f, amax = 0.f, l1 = 0.f;
    #pragma unroll
    for (int i = 0; i < 16; i++) {
        float4 a = r[i];
        en += a.x * a.x + a.y * a.y + a.z * a.z + a.w * a.w;  // validated order
        l1 += fabsf(a.x) + fabsf(a.y) + fabsf(a.z) + fabsf(a.w);
        amax = fmaxf(amax, fabsf(a.x)); amax = fmaxf(amax, fabsf(a.y));
        amax = fmaxf(amax, fabsf(a.z)); amax = fmaxf(amax, fabsf(a.w));
    }
    float sw = amax * (1.f / 127.f);
    float rs = (amax > 0.f) ? (127.f / amax) : 0.f;
    #pragma unroll
    for (int i = 0; i < 16; i++) {
        float4 a = r[i];
        g_pack[k * 16 + i] = pack4(q8(a.x, rs), q8(a.y, rs), q8(a.z, rs), q8(a.w, rs));
    }
    g_pack[16384 + 2 * k]     = __float_as_uint(en);
    g_pack[16384 + 2 * k + 1] = __float_as_uint(sw);
    // half L1w, inflated before rounding so the stored value upper-bounds l1
    unsigned short hl = __half_as_ushort(__float2half_rn(l1 * 1.001f + 1e-6f));
    if (k % 2 == 0) atomicAnd(&g_pack[18432 + k / 2], 0xFFFF0000u);
    // write both halves race-free: each k owns 16 bits
    atomicOr(&g_pack[18432 + k / 2], (uint32_t)hl << ((k & 1) * 16));
}

// ---------------- main VQ kernel (finalize fused in last block) ----------------
__global__ __launch_bounds__(THREADS, 3) void vq_kernel(
    const float* __restrict__ x, const float* __restrict__ w, float* __restrict__ out)
{
    extern __shared__ uint8_t dyn[];
    uint32_t*      s_qw = (uint32_t*)dyn;                 // 65536 B
    const float2*  s_ms = (const float2*)(dyn + 65536);   //  8192 B {en, sw}
    const __half*  s_l1 = (const __half*)(dyn + 73728);   //  2048 B
    __shared__ float s_warp[8];
    __shared__ unsigned s_ticket;

    const int tid  = threadIdx.x;
    const int gtok = blockIdx.x * MT + tid;
    const float4* xr = (const float4*)(x + (size_t)gtok * DIM);
    uint32_t* myc = g_cand + (size_t)gtok * CAP;

    // stage packed codebook + meta (4736 uint4)
    {
        const uint4* src = (const uint4*)g_pack;
        uint4* dst = (uint4*)dyn;
        #pragma unroll
        for (int i = 0; i < 18; i++) dst[i * 256 + tid] = src[i * 256 + tid];
        if (tid < 128) dst[18 * 256 + tid] = src[18 * 256 + tid];
    }

    // pass 1 over x row: amax + xn (validated accumulation order for xn)
    float xn = 0.f, amax = 0.f;
    #pragma unroll
    for (int i = 0; i < 16; i++) {
        float4 v = xr[i];
        xn += v.x * v.x + v.y * v.y + v.z * v.z + v.w * v.w;
        amax = fmaxf(amax, fabsf(v.x)); amax = fmaxf(amax, fabsf(v.y));
        amax = fmaxf(amax, fabsf(v.z)); amax = fmaxf(amax, fabsf(v.w));
    }
    // pass 2: quantize own token (L1 hits); sabs = sum|qx|
    uint32_t qx[16];
    int sabs = 0;
    const float sx = amax * (1.f / 127.f);
    {
        const float rs = (amax > 0.f) ? (127.f / amax) : 0.f;
        #pragma unroll
        for (int i = 0; i < 16; i++) {
            float4 v = xr[i];
            int a = q8(v.x, rs), b = q8(v.y, rs), c = q8(v.z, rs), d = q8(v.w, rs);
            sabs += abs(a) + abs(b) + abs(c) + abs(d);
            qx[i] = pack4(a, b, c, d);
        }
    }
    __syncthreads();

    // R10-validated rigorous bound: |s~-s'| <= e1*L1w_k + e2*sw_k (+slack)
    const float e1 = sx * 1.0001f;
    const float e2 = (sx * (float)sabs) * 1.0001f;
    const float nC = -2.f * sx;
    float best_ub = 3.4e38f;
    int cnt = 0;
    #pragma unroll 2
    for (int k = 0; k < KC; k++) {
        const uint4* row = (const uint4*)(s_qw + k * 16);
        uint4 a = row[0], b = row[1], c = row[2], d = row[3];
        int p0 = 0, p1 = 0, p2 = 0, p3 = 0;
        p0 = __dp4a((int)a.x, (int)qx[0],  p0);
        p1 = __dp4a((int)a.y, (int)qx[1],  p1);
        p2 = __dp4a((int)a.z, (int)qx[2],  p2);
        p3 = __dp4a((int)a.w, (int)qx[3],  p3);
        p0 = __dp4a((int)b.x, (int)qx[4],  p0);
        p1 = __dp4a((int)b.y, (int)qx[5],  p1);
        p2 = __dp4a((int)b.z, (int)qx[6],  p2);
        p3 = __dp4a((int)b.w, (int)qx[7],  p3);
        p0 = __dp4a((int)c.x, (int)qx[8],  p0);
        p1 = __dp4a((int)c.y, (int)qx[9],  p1);
        p2 = __dp4a((int)c.z, (int)qx[10], p2);
        p3 = __dp4a((int)c.w, (int)qx[11], p3);
        p0 = __dp4a((int)d.x, (int)qx[12], p0);
        p1 = __dp4a((int)d.y, (int)qx[13], p1);
        p2 = __dp4a((int)d.z, (int)qx[14], p2);
        p3 = __dp4a((int)d.w, (int)qx[15], p3);
        int idot = (p0 + p1) + (p2 + p3);
        float2 m = s_ms[k];
        float l1w = __half2float(s_l1[k]);             // >= true L1 norm
        float s = fmaf(nC * m.y, (float)idot, m.x);    // approx score (no xn)
        float E = fmaf(e1, l1w, e2 * m.y) + 1e-4f;     // rigorous bound
        float lb = s - E;
        if (lb <= best_ub) {                           // provable superset keep
            if (cnt < CAP) {
                uint32_t h = (uint32_t)__half_as_ushort(__float2half(lb));
                myc[cnt] = (h << 16) | (uint32_t)k;
            }
            cnt++;
        }
        best_ub = fminf(best_ub, s + E);
    }

    // ---- exact rescore (statement-identical to validated path) ----
    float bestex = 3.4e38f;
    int bi = 0;
    auto rescore = [&](int k) {
        const float4* wr = (const float4*)(w + (size_t)k * DIM);
        float a0 = 0.f, a1 = 0.f, a2 = 0.f, a3 = 0.f;
        #pragma unroll
        for (int p = 0; p < 16; p++) {
            float4 xv = xr[p];
            float4 wv = wr[p];
            a0 = fmaf(xv.x, wv.x, a0);
            a1 = fmaf(xv.y, wv.y, a1);
            a2 = fmaf(xv.z, wv.z, a2);
            a3 = fmaf(xv.w, wv.w, a3);
        }
        float dot = __fadd_rn(__fadd_rn(a0, a1), __fadd_rn(a2, a3));
        float s = __fadd_rn(__fadd_rn(xn, s_ms[k].x), -2.f * dot);
        if (s < bestex || (s == bestex && k < bi)) { bestex = s; bi = k; }
    };

    if (cnt > CAP) {
        for (int k = 0; k < KC; k++) rescore(k);       // P < 1e-20: dead safety
    } else {
        const float fth = best_ub + 1e-3f;             // fp16 round-up slack
        for (int i = 0; i < cnt; i++) {                // ascending k order
            uint32_t e = myc[i];                       // L2-hit readback
            float lb = __half2float(__ushort_as_half((unsigned short)(e >> 16)));
            if (lb <= fth) rescore((int)(e & 0xFFFFu));
        }
    }

    // ---- outputs (validated epilogue) ----
    const float4* wrow = (const float4*)(w + (size_t)bi * DIM);
    float4* xqo = (float4*)(out + (size_t)gtok * DIM);
    float err = 0.f;
    #pragma unroll
    for (int i = 0; i < 16; i++) {
        float4 xv = xr[i];
        float4 wv = wrow[i];
        float e0 = wv.x - xv.x, t1 = wv.y - xv.y;
        float t2 = wv.z - xv.z, t3 = wv.w - xv.w;
        err += e0 * e0 + t1 * t1 + t2 * t2 + t3 * t3;
        xqo[i] = wv;
    }
    out[(size_t)NT * DIM + 1 + gtok] = (float)bi;

    #pragma unroll
    for (int o = 16; o > 0; o >>= 1) err += __shfl_xor_sync(0xffffffffu, err, o);
    if ((tid & 31) == 0) s_warp[tid >> 5] = err;
    __syncthreads();
    if (tid == 0) {
        float s = 0.f;
        #pragma unroll
        for (int i = 0; i < 8; i++) s += s_warp[i];
        g_partials[blockIdx.x] = s;
    }

    // ---- fused finalize (identical double-reduction arithmetic) ----
    __threadfence();
    if (tid == 0) s_ticket = atomicAdd(&g_ctr, 1u);
    __syncthreads();
    if (s_ticket == GRID_VQ - 1) {
        double* sd = (double*)(dyn + 65536);   // reuse meta region (done)
        double v = 0.0;
        for (int i = tid; i < GRID_VQ; i += 256) v += (double)g_partials[i];
        sd[tid] = v;
        __syncthreads();
        for (int o = 128; o > 0; o >>= 1) {
            if (tid < o) sd[tid] += sd[tid + o];
            __syncthreads();
        }
        if (tid == 0) {
            double mse = sd[0] / ((double)NT * (double)DIM);
            out[(size_t)NT * DIM] = (float)(1.25 * mse);
            g_ctr = 0;                          // self-reset for graph replay
        }
    }
}

// pads keep vq_kernel at in-call launch index 3 (ncu -s 5 lands on vq)
__global__ void pad0_kernel() {}
__global__ void pad1_kernel() {}

extern "C" void kernel_launch(void* const* d_in, const int* in_sizes, int n_in,
                              void* d_out, int out_size) {
    const float* x = (const float*)d_in[0];
    const float* w = (const float*)d_in[1];
    float* out = (float*)d_out;
    cudaFuncSetAttribute((const void*)vq_kernel,
                         cudaFuncAttributeMaxDynamicSharedMemorySize, 75776);
    prep_kernel<<<4, 256>>>(w);
    pad0_kernel<<<1, 32>>>();
    pad1_kernel<<<1, 32>>>();
    vq_kernel<<<GRID_VQ, THREADS, 75776>>>(x, w, out);
}

// round 15
// speedup vs baseline: 1.9909x; 1.1469x over previous
#include <cuda_runtime.h>
#include <cstdint>

// R14: all-integer dp4a prune. Global quant scales (sx_g, sw_g) make the score
// comparison pure int (seeded dp4a + ISETP) - no I2F / fp chain / half unpack
// in the hot loop. Candidates back in SMEM, proven 2-CTA/127-reg config.
// Exact rescore / epilogue / finalize statement-identical to validated path.

#define NT       131072
#define KC       1024
#define DIM      64
#define MT       256
#define THREADS  256
#define GRID_VQ  (NT/MT)          // 512
#define CAP      32
#define SI_BIAS  (1 << 21)

// g_pack: [0,16384) int8 rows (global scale); [16384,17408) en_int;
// [17408,18432) exact fp32 e_norm bits.
__device__ uint32_t g_pack[18432];
__device__ uint32_t g_xamax;      // global |x| max (float bits, monotone)
__device__ uint32_t g_wamax;      // global row-|w| max
__device__ uint32_t g_l1wmax;     // max row L1 norm
__device__ float g_partials[GRID_VQ];
__device__ unsigned g_ctr = 0;

static __device__ __forceinline__ int q8(float v, float rs) {
    int q = __float2int_rn(v * rs);
    return max(-127, min(127, q));
}
static __device__ __forceinline__ uint32_t pack4(int a, int b, int c, int d) {
    return (uint32_t)(uint8_t)a | ((uint32_t)(uint8_t)b << 8) |
           ((uint32_t)(uint8_t)c << 16) | ((uint32_t)(uint8_t)d << 24);
}

// ---------------- prepA: global amax of x and of w rows ----------------
__global__ void prepA_kernel(const float* __restrict__ x, const float* __restrict__ w) {
    int tid = blockIdx.x * 256 + threadIdx.x;          // 512*256 threads
    const float4* xr = (const float4*)x;               // 2,097,152 float4
    float am = 0.f;
    #pragma unroll
    for (int i = 0; i < 16; i++) {
        float4 v = xr[(size_t)tid * 16 + i];
        am = fmaxf(am, fmaxf(fmaxf(fabsf(v.x), fabsf(v.y)),
                             fmaxf(fabsf(v.z), fabsf(v.w))));
    }
    #pragma unroll
    for (int o = 16; o > 0; o >>= 1) am = fmaxf(am, __shfl_xor_sync(0xffffffffu, am, o));
    if ((threadIdx.x & 31) == 0) atomicMax(&g_xamax, __float_as_uint(am));
    if (tid < KC) {                                    // one thread per w row
        const float4* r = (const float4*)(w + (size_t)tid * DIM);
        float wa = 0.f;
        #pragma unroll
        for (int i = 0; i < 16; i++) {
            float4 a = r[i];
            wa = fmaxf(wa, fmaxf(fmaxf(fabsf(a.x), fabsf(a.y)),
                                 fmaxf(fabsf(a.z), fabsf(a.w))));
        }
        atomicMax(&g_wamax, __float_as_uint(wa));
    }
}

// ---------------- prepB: quantize w (global scale) + en_int + exact en ----------------
__global__ void prepB_kernel(const float* __restrict__ w) {
    int k = blockIdx.x * 256 + threadIdx.x;
    if (k >= KC) return;
    const float sxg = __uint_as_float(g_xamax) * (1.f / 127.f);
    const float wam = __uint_as_float(g_wamax);
    const float swg = wam * (1.f / 127.f);
    const float rs  = (wam > 0.f) ? (127.f / wam) : 0.f;
    const float4* r = (const float4*)(w + (size_t)k * DIM);
    float en = 0.f, l1 = 0.f;
    #pragma unroll
    for (int i = 0; i < 16; i++) {
        float4 a = r[i];
        en += a.x * a.x + a.y * a.y + a.z * a.z + a.w * a.w;   // validated order
        l1 += fabsf(a.x) + fabsf(a.y) + fabsf(a.z) + fabsf(a.w);
        g_pack[k * 16 + i] = pack4(q8(a.x, rs), q8(a.y, rs), q8(a.z, rs), q8(a.w, rs));
    }
    const float inv2C = 1.f / (2.f * sxg * swg);
    g_pack[16384 + k] = (uint32_t)__float2int_rn(en * inv2C);  // en_int
    g_pack[17408 + k] = __float_as_uint(en);                   // exact en
    atomicMax(&g_l1wmax, __float_as_uint(l1));
}

// ---------------- main VQ kernel (finalize fused in last block) ----------------
__global__ __launch_bounds__(THREADS, 2) void vq_kernel(
    const float* __restrict__ x, const float* __restrict__ w, float* __restrict__ out)
{
    extern __shared__ uint8_t dyn[];
    uint32_t*   s_qw  = (uint32_t*)dyn;              // 65536 B
    const int*  s_eni = (const int*)(dyn + 65536);   //  4096 B en_int
    const float* s_enf = (const float*)(dyn + 69632);//  4096 B exact en
    uint32_t*   s_cand = (uint32_t*)(dyn + 73728);   // 32768 B (256*CAP)
    __shared__ float s_warp[8];
    __shared__ unsigned s_ticket;

    const int tid  = threadIdx.x;
    const int gtok = blockIdx.x * MT + tid;
    const float4* xr = (const float4*)(x + (size_t)gtok * DIM);

    // stage packed codebook + meta (4608 uint4)
    {
        const uint4* src = (const uint4*)g_pack;
        uint4* dst = (uint4*)dyn;
        #pragma unroll
        for (int i = 0; i < 18; i++) dst[i * 256 + tid] = src[i * 256 + tid];
    }

    const float sxg = __uint_as_float(g_xamax) * (1.f / 127.f);
    const float swg = __uint_as_float(g_wamax) * (1.f / 127.f);
    const float l1m = __uint_as_float(g_l1wmax);

    // single pass over x row: xn (validated order) + NEGATED global-scale quant
    float xn = 0.f;
    uint32_t qxn[16];
    int sx1 = 0;
    {
        const float rsx = 127.f / __uint_as_float(g_xamax);
        #pragma unroll
        for (int i = 0; i < 16; i++) {
            float4 v = xr[i];
            xn += v.x * v.x + v.y * v.y + v.z * v.z + v.w * v.w;
            int a = q8(v.x, rsx), b = q8(v.y, rsx), c = q8(v.z, rsx), d = q8(v.w, rsx);
            sx1 += abs(a) + abs(b) + abs(c) + abs(d);
            qxn[i] = pack4(-a, -b, -c, -d);
        }
    }
    __syncthreads();

    // Rigorous int window: |s' - 2C*si| <= C*(1+sx1) + sxg*L1w_max
    //   => W_int = 0.5*(1+sx1) + L1w_max/(2*swg)  (x1.02 + 4 slack); test si<=m+2W
    const float Wf = 0.5f * (1.f + (float)sx1) + l1m / (2.f * swg);
    const int W2 = 2 * ((int)(Wf * 1.02f) + 4);

    int m = 1 << 29, thr = 1 << 29, cnt = 0;
    #pragma unroll 2
    for (int k = 0; k < KC; k++) {
        const uint4* row = (const uint4*)(s_qw + k * 16);
        uint4 a = row[0], b = row[1], c = row[2], d = row[3];
        int p0 = s_eni[k], p1 = 0, p2 = 0, p3 = 0;     // seed with en_int
        p0 = __dp4a((int)a.x, (int)qxn[0],  p0);
        p1 = __dp4a((int)a.y, (int)qxn[1],  p1);
        p2 = __dp4a((int)a.z, (int)qxn[2],  p2);
        p3 = __dp4a((int)a.w, (int)qxn[3],  p3);
        p0 = __dp4a((int)b.x, (int)qxn[4],  p0);
        p1 = __dp4a((int)b.y, (int)qxn[5],  p1);
        p2 = __dp4a((int)b.z, (int)qxn[6],  p2);
        p3 = __dp4a((int)b.w, (int)qxn[7],  p3);
        p0 = __dp4a((int)c.x, (int)qxn[8],  p0);
        p1 = __dp4a((int)c.y, (int)qxn[9],  p1);
        p2 = __dp4a((int)c.z, (int)qxn[10], p2);
        p3 = __dp4a((int)c.w, (int)qxn[11], p3);
        p0 = __dp4a((int)d.x, (int)qxn[12], p0);
        p1 = __dp4a((int)d.y, (int)qxn[13], p1);
        p2 = __dp4a((int)d.z, (int)qxn[14], p2);
        p3 = __dp4a((int)d.w, (int)qxn[15], p3);
        int si = (p0 + p1) + (p2 + p3);                // = en_int - idot (exact int)
        if (si <= thr) {                               // provable superset keep
            if (cnt < CAP)
                s_cand[tid * CAP + cnt] =
                    ((uint32_t)(si + SI_BIAS) << 10) | (uint32_t)k;
            cnt++;
            if (si < m) { m = si; thr = m + W2; }
        }
    }

    // ---- exact rescore (statement-identical to validated path) ----
    float bestex = 3.4e38f;
    int bi = 0;
    auto rescore = [&](int k) {
        const float4* wr = (const float4*)(w + (size_t)k * DIM);
        float a0 = 0.f, a1 = 0.f, a2 = 0.f, a3 = 0.f;
        #pragma unroll
        for (int p = 0; p < 16; p++) {
            float4 xv = xr[p];
            float4 wv = wr[p];
            a0 = fmaf(xv.x, wv.x, a0);
            a1 = fmaf(xv.y, wv.y, a1);
            a2 = fmaf(xv.z, wv.z, a2);
            a3 = fmaf(xv.w, wv.w, a3);
        }
        float dot = __fadd_rn(__fadd_rn(a0, a1), __fadd_rn(a2, a3));
        float s = __fadd_rn(__fadd_rn(xn, s_enf[k]), -2.f * dot);
        if (s < bestex || (s == bestex && k < bi)) { bestex = s; bi = k; }
    };

    if (cnt > CAP) {
        for (int k = 0; k < KC; k++) rescore(k);       // P ~ 1e-12: dead safety
    } else {
        const int thrF = m + W2;                       // final tight filter
        for (int i = 0; i < cnt; i++) {                // ascending k order
            uint32_t e = s_cand[tid * CAP + i];
            int si = (int)(e >> 10) - SI_BIAS;
            if (si <= thrF) rescore((int)(e & 1023u));
        }
    }

    // ---- outputs (validated epilogue) ----
    const float4* wrow = (const float4*)(w + (size_t)bi * DIM);
    float4* xqo = (float4*)(out + (size_t)gtok * DIM);
    float err = 0.f;
    #pragma unroll
    for (int i = 0; i < 16; i++) {
        float4 xv = xr[i];
        float4 wv = wrow[i];
        float e0 = wv.x - xv.x, t1 = wv.y - xv.y;
        float t2 = wv.z - xv.z, t3 = wv.w - xv.w;
        err += e0 * e0 + t1 * t1 + t2 * t2 + t3 * t3;
        xqo[i] = wv;
    }
    out[(size_t)NT * DIM + 1 + gtok] = (float)bi;

    #pragma unroll
    for (int o = 16; o > 0; o >>= 1) err += __shfl_xor_sync(0xffffffffu, err, o);
    if ((tid & 31) == 0) s_warp[tid >> 5] = err;
    __syncthreads();
    if (tid == 0) {
        float s = 0.f;
        #pragma unroll
        for (int i = 0; i < 8; i++) s += s_warp[i];
        g_partials[blockIdx.x] = s;
    }

    // ---- fused finalize (identical double-reduction arithmetic) ----
    __threadfence();
    if (tid == 0) s_ticket = atomicAdd(&g_ctr, 1u);
    __syncthreads();
    if (s_ticket == GRID_VQ - 1) {
        double* sd = (double*)(dyn + 73728);   // reuse candidate region (done)
        double v = 0.0;
        for (int i = tid; i < GRID_VQ; i += 256) v += (double)g_partials[i];
        sd[tid] = v;
        __syncthreads();
        for (int o = 128; o > 0; o >>= 1) {
            if (tid < o) sd[tid] += sd[tid + o];
            __syncthreads();
        }
        if (tid == 0) {
            double mse = sd[0] / ((double)NT * (double)DIM);
            out[(size_t)NT * DIM] = (float)(1.25 * mse);
            g_ctr = 0;                          // self-reset for graph replay
        }
    }
}

// pad keeps vq_kernel at in-call launch index 3 (ncu -s 5 lands on vq)
__global__ void pad0_kernel() {}

extern "C" void kernel_launch(void* const* d_in, const int* in_sizes, int n_in,
                              void* d_out, int out_size) {
    const float* x = (const float*)d_in[0];
    const float* w = (const float*)d_in[1];
    float* out = (float*)d_out;
    cudaFuncSetAttribute((const void*)vq_kernel,
                         cudaFuncAttributeMaxDynamicSharedMemorySize, 106496);
    prepA_kernel<<<512, 256>>>(x, w);
    prepB_kernel<<<4, 256>>>(w);
    pad0_kernel<<<1, 32>>>();
    vq_kernel<<<GRID_VQ, THREADS, 106496>>>(x, w, out);
}

// round 16
// speedup vs baseline: 8.4910x; 4.2650x over previous
#include <cuda_runtime.h>
#include <cstdint>

// R15: R10's tight per-row bound + CAP=64 ushort SMEM candidates with
// rescore-all (no stored scores) => warp-divergent full-KC fallback is
// structurally dead (P<1e-15). Every round since R10 was dominated by that
// fallback (fma% forensics). Proven 2-CTA / 106KB config.
// Exact rescore / epilogue / finalize statement-identical to validated path.

#define NT       131072
#define KC       1024
#define DIM      64
#define MT       256
#define THREADS  256
#define GRID_VQ  (NT/MT)          // 512
#define CAP      64

// g_pack: [0,16384) int8 rows (per-row scale); [16384,18432) float2 {en, sw}.
__device__ uint32_t g_pack[18432];
__device__ uint32_t g_l1wmax;     // max row L1 norm (float bits, monotone max)
__device__ float g_partials[GRID_VQ];
__device__ unsigned g_ctr = 0;

static __device__ __forceinline__ int q8(float v, float rs) {
    int q = __float2int_rn(v * rs);
    return max(-127, min(127, q));
}
static __device__ __forceinline__ uint32_t pack4(int a, int b, int c, int d) {
    return (uint32_t)(uint8_t)a | ((uint32_t)(uint8_t)b << 8) |
           ((uint32_t)(uint8_t)c << 16) | ((uint32_t)(uint8_t)d << 24);
}

// ---------------- prep: per-row int8 quant + exact e_norm + L1 max ----------------
__global__ void prep_kernel(const float* __restrict__ w) {
    int k = blockIdx.x * 256 + threadIdx.x;
    if (k >= KC) return;
    const float4* r = (const float4*)(w + (size_t)k * DIM);
    float en = 0.f, amax = 0.f, l1 = 0.f;
    #pragma unroll
    for (int i = 0; i < 16; i++) {
        float4 a = r[i];
        en += a.x * a.x + a.y * a.y + a.z * a.z + a.w * a.w;  // validated order
        l1 += fabsf(a.x) + fabsf(a.y) + fabsf(a.z) + fabsf(a.w);
        amax = fmaxf(amax, fabsf(a.x)); amax = fmaxf(amax, fabsf(a.y));
        amax = fmaxf(amax, fabsf(a.z)); amax = fmaxf(amax, fabsf(a.w));
    }
    float sw = amax * (1.f / 127.f);
    float rs = (amax > 0.f) ? (127.f / amax) : 0.f;
    #pragma unroll
    for (int i = 0; i < 16; i++) {
        float4 a = r[i];
        g_pack[k * 16 + i] = pack4(q8(a.x, rs), q8(a.y, rs), q8(a.z, rs), q8(a.w, rs));
    }
    g_pack[16384 + 2 * k]     = __float_as_uint(en);
    g_pack[16384 + 2 * k + 1] = __float_as_uint(sw);
    atomicMax(&g_l1wmax, __float_as_uint(l1 * 1.001f));   // inflated upper bound
}

// ---------------- main VQ kernel (finalize fused in last block) ----------------
__global__ __launch_bounds__(THREADS, 2) void vq_kernel(
    const float* __restrict__ x, const float* __restrict__ w, float* __restrict__ out)
{
    extern __shared__ uint8_t dyn[];
    uint32_t*       s_qw = (uint32_t*)dyn;               // 65536 B
    const float2*   s_ms = (const float2*)(dyn + 65536); //  8192 B {en, sw}
    unsigned short* s_ck = (unsigned short*)(dyn + 73728); // 32768 B (256*CAP)
    __shared__ float s_warp[8];
    __shared__ unsigned s_ticket;

    const int tid  = threadIdx.x;
    const int gtok = blockIdx.x * MT + tid;
    const float4* xr = (const float4*)(x + (size_t)gtok * DIM);

    // stage packed codebook + meta (4608 uint4)
    {
        const uint4* src = (const uint4*)g_pack;
        uint4* dst = (uint4*)dyn;
        #pragma unroll
        for (int i = 0; i < 18; i++) dst[i * 256 + tid] = src[i * 256 + tid];
    }

    // pass 1 over x row: amax + xn (validated accumulation order for xn)
    float xn = 0.f, amax = 0.f;
    #pragma unroll
    for (int i = 0; i < 16; i++) {
        float4 v = xr[i];
        xn += v.x * v.x + v.y * v.y + v.z * v.z + v.w * v.w;
        amax = fmaxf(amax, fabsf(v.x)); amax = fmaxf(amax, fabsf(v.y));
        amax = fmaxf(amax, fabsf(v.z)); amax = fmaxf(amax, fabsf(v.w));
    }
    // pass 2: quantize own token (L1 hits); sabs = sum|qx|
    uint32_t qx[16];
    int sabs = 0;
    const float sx = amax * (1.f / 127.f);
    {
        const float rs = (amax > 0.f) ? (127.f / amax) : 0.f;
        #pragma unroll
        for (int i = 0; i < 16; i++) {
            float4 v = xr[i];
            int a = q8(v.x, rs), b = q8(v.y, rs), c = q8(v.z, rs), d = q8(v.w, rs);
            sabs += abs(a) + abs(b) + abs(c) + abs(d);
            qx[i] = pack4(a, b, c, d);
        }
    }
    __syncthreads();

    // Rigorous bound (R10-validated, L1w relaxed to global max):
    //   |s~ - s'| <= e1*L1w_max + e2*sw_k    (+ slack)
    const float E1 = (sx * 1.0001f) * __uint_as_float(g_l1wmax) + 1e-4f;
    const float e2 = (sx * (float)sabs) * 1.0001f;
    const float nC = -2.f * sx;
    float best_ub = 3.4e38f;
    int cnt = 0;
    #pragma unroll 2
    for (int k = 0; k < KC; k++) {
        const uint4* row = (const uint4*)(s_qw + k * 16);
        uint4 a = row[0], b = row[1], c = row[2], d = row[3];
        int p0 = 0, p1 = 0, p2 = 0, p3 = 0;
        p0 = __dp4a((int)a.x, (int)qx[0],  p0);
        p1 = __dp4a((int)a.y, (int)qx[1],  p1);
        p2 = __dp4a((int)a.z, (int)qx[2],  p2);
        p3 = __dp4a((int)a.w, (int)qx[3],  p3);
        p0 = __dp4a((int)b.x, (int)qx[4],  p0);
        p1 = __dp4a((int)b.y, (int)qx[5],  p1);
        p2 = __dp4a((int)b.z, (int)qx[6],  p2);
        p3 = __dp4a((int)b.w, (int)qx[7],  p3);
        p0 = __dp4a((int)c.x, (int)qx[8],  p0);
        p1 = __dp4a((int)c.y, (int)qx[9],  p1);
        p2 = __dp4a((int)c.z, (int)qx[10], p2);
        p3 = __dp4a((int)c.w, (int)qx[11], p3);
        p0 = __dp4a((int)d.x, (int)qx[12], p0);
        p1 = __dp4a((int)d.y, (int)qx[13], p1);
        p2 = __dp4a((int)d.z, (int)qx[14], p2);
        p3 = __dp4a((int)d.w, (int)qx[15], p3);
        int idot = (p0 + p1) + (p2 + p3);
        float2 m = s_ms[k];
        float s = fmaf(nC * m.y, (float)idot, m.x);    // approx score (no xn)
        float E = fmaf(e2, m.y, E1);                   // rigorous bound
        if (s - E <= best_ub) {                        // provable superset keep
            if (cnt < CAP) s_ck[tid * CAP + cnt] = (unsigned short)k;
            cnt++;
        }
        best_ub = fminf(best_ub, s + E);
    }

    // ---- exact rescore of ALL collected candidates (validated semantics) ----
    float bestex = 3.4e38f;
    int bi = 0;
    auto rescore = [&](int k) {
        const float4* wr = (const float4*)(w + (size_t)k * DIM);
        float a0 = 0.f, a1 = 0.f, a2 = 0.f, a3 = 0.f;
        #pragma unroll
        for (int p = 0; p < 16; p++) {
            float4 xv = xr[p];
            float4 wv = wr[p];
            a0 = fmaf(xv.x, wv.x, a0);
            a1 = fmaf(xv.y, wv.y, a1);
            a2 = fmaf(xv.z, wv.z, a2);
            a3 = fmaf(xv.w, wv.w, a3);
        }
        float dot = __fadd_rn(__fadd_rn(a0, a1), __fadd_rn(a2, a3));
        float s = __fadd_rn(__fadd_rn(xn, s_ms[k].x), -2.f * dot);
        if (s < bestex || (s == bestex && k < bi)) { bestex = s; bi = k; }
    };

    if (cnt > CAP) {
        for (int k = 0; k < KC; k++) rescore(k);       // P < 1e-15: dead safety
    } else {
        for (int i = 0; i < cnt; i++)                  // ascending k order
            rescore((int)s_ck[tid * CAP + i]);
    }

    // ---- outputs (validated epilogue) ----
    const float4* wrow = (const float4*)(w + (size_t)bi * DIM);
    float4* xqo = (float4*)(out + (size_t)gtok * DIM);
    float err = 0.f;
    #pragma unroll
    for (int i = 0; i < 16; i++) {
        float4 xv = xr[i];
        float4 wv = wrow[i];
        float e0 = wv.x - xv.x, t1 = wv.y - xv.y;
        float t2 = wv.z - xv.z, t3 = wv.w - xv.w;
        err += e0 * e0 + t1 * t1 + t2 * t2 + t3 * t3;
        xqo[i] = wv;
    }
    out[(size_t)NT * DIM + 1 + gtok] = (float)bi;

    #pragma unroll
    for (int o = 16; o > 0; o >>= 1) err += __shfl_xor_sync(0xffffffffu, err, o);
    if ((tid & 31) == 0) s_warp[tid >> 5] = err;
    __syncthreads();
    if (tid == 0) {
        float s = 0.f;
        #pragma unroll
        for (int i = 0; i < 8; i++) s += s_warp[i];
        g_partials[blockIdx.x] = s;
    }

    // ---- fused finalize (identical double-reduction arithmetic) ----
    __threadfence();
    if (tid == 0) s_ticket = atomicAdd(&g_ctr, 1u);
    __syncthreads();
    if (s_ticket == GRID_VQ - 1) {
        double* sd = (double*)(dyn + 73728);   // reuse candidate region (done)
        double v = 0.0;
        for (int i = tid; i < GRID_VQ; i += 256) v += (double)g_partials[i];
        sd[tid] = v;
        __syncthreads();
        for (int o = 128; o > 0; o >>= 1) {
            if (tid < o) sd[tid] += sd[tid + o];
            __syncthreads();
        }
        if (tid == 0) {
            double mse = sd[0] / ((double)NT * (double)DIM);
            out[(size_t)NT * DIM] = (float)(1.25 * mse);
            g_ctr = 0;                          // self-reset for graph replay
        }
    }
}

// pads keep vq_kernel at in-call launch index 3 (empirically where ncu lands)
__global__ void pad0_kernel() {}
__global__ void pad1_kernel() {}

extern "C" void kernel_launch(void* const* d_in, const int* in_sizes, int n_in,
                              void* d_out, int out_size) {
    const float* x = (const float*)d_in[0];
    const float* w = (const float*)d_in[1];
    float* out = (float*)d_out;
    cudaFuncSetAttribute((const void*)vq_kernel,
                         cudaFuncAttributeMaxDynamicSharedMemorySize, 106496);
    prep_kernel<<<4, 256>>>(w);
    pad0_kernel<<<1, 32>>>();
    pad1_kernel<<<1, 32>>>();
    vq_kernel<<<GRID_VQ, THREADS, 106496>>>(x, w, out);
}